// round 6
// baseline (speedup 1.0000x reference)
#include <cuda_runtime.h>
#include <cstdint>

#define BB 2
#define TT 2048
#define CCH 1024
#define HH 16
#define DD 64
#define MROWS (BB * TT)       // 4096
#define NEG_BIG (-1e30f)

// Scratch
__device__ float g_qkv[(size_t)MROWS * 3 * CCH];   // rounded tf32 after GEMM1
__device__ float g_att[(size_t)MROWS * CCH];       // rounded tf32 after attention
__device__ float g_x32[(size_t)MROWS * CCH];       // x rounded tf32
__device__ float g_wqkv[(size_t)CCH * 3 * CCH];    // Wqkv rounded tf32
__device__ float g_wproj[(size_t)CCH * CCH];       // Wproj rounded tf32

// ---------------------------------------------------------------------------
// Helpers
// ---------------------------------------------------------------------------
__device__ __forceinline__ float tf32r(float f) {
    uint32_t r;
    asm("cvt.rna.tf32.f32 %0, %1;" : "=r"(r) : "f"(f));
    return __uint_as_float(r);
}
__device__ __forceinline__ uint32_t fb(float f) { return __float_as_uint(f); }
__device__ __forceinline__ uint32_t sptr(const void* p) {
    return (uint32_t)__cvta_generic_to_shared(p);
}
__device__ __forceinline__ void cpa16(uint32_t d, const void* s) {
    asm volatile("cp.async.ca.shared.global [%0], [%1], 16;" :: "r"(d), "l"(s));
}
#define CP_COMMIT() asm volatile("cp.async.commit_group;" ::)
#define CP_WAIT(N)  asm volatile("cp.async.wait_group %0;" :: "n"(N))

__device__ __forceinline__ void mma_tf32(float c[4], const uint32_t a[4],
                                         uint32_t b0, uint32_t b1) {
    asm volatile(
        "mma.sync.aligned.m16n8k8.row.col.f32.tf32.tf32.f32 "
        "{%0,%1,%2,%3}, {%4,%5,%6,%7}, {%8,%9}, {%0,%1,%2,%3};\n"
        : "+f"(c[0]), "+f"(c[1]), "+f"(c[2]), "+f"(c[3])
        : "r"(a[0]), "r"(a[1]), "r"(a[2]), "r"(a[3]), "r"(b0), "r"(b1));
}

// ---------------------------------------------------------------------------
// tf32 pre-round kernel (float4 grid-stride)
// ---------------------------------------------------------------------------
__global__ void cvt_tf32_kernel(const float* __restrict__ src, float* __restrict__ dst,
                                int n4) {
    int i = blockIdx.x * blockDim.x + threadIdx.x;
    if (i < n4) {
        float4 v = reinterpret_cast<const float4*>(src)[i];
        float4 o = {tf32r(v.x), tf32r(v.y), tf32r(v.z), tf32r(v.w)};
        reinterpret_cast<float4*>(dst)[i] = o;
    }
}

// ---------------------------------------------------------------------------
// TF32 GEMM + bias, inputs pre-rounded to tf32.
// 256 threads (8 warps), block tile 128(M) x 256(N), warp tile 64x64, BK=16.
// cp.async 2-stage double buffer. A smem [m][k] stride 20; B smem [k][n] stride 264.
// roundOut: round outputs to tf32 (for qkv feeding attention).
// ---------------------------------------------------------------------------
#define BSA 20
#define BSB 264
#define GEMM_SMEM ((2 * 128 * BSA + 2 * 16 * BSB) * 4)

__global__ __launch_bounds__(256)
void gemm_tf32_cp(const float* __restrict__ A, const float* __restrict__ B,
                  const float* __restrict__ bias, float* __restrict__ C,
                  int M, int N, int K, int roundOut) {
    extern __shared__ float sm[];
    float* AsBase = sm;                    // [2][128][BSA]
    float* BsBase = sm + 2 * 128 * BSA;    // [2][16][BSB]

    const int tid = threadIdx.x;
    const int w = tid >> 5, lane = tid & 31;
    const int g = lane >> 2, tg = lane & 3;
    const int wm = (w & 1) * 64, wn = (w >> 1) * 64;
    const int rowBase = blockIdx.y * 128;
    const int colBase = blockIdx.x * 256;

    // cp.async chunk indices
    int aRow[2], aC4[2], bRow[4], bC4[4];
#pragma unroll
    for (int i = 0; i < 2; i++) {
        int idx = i * 256 + tid;
        aRow[i] = idx >> 2; aC4[i] = (idx & 3) * 4;
    }
#pragma unroll
    for (int i = 0; i < 4; i++) {
        int idx = i * 256 + tid;
        bRow[i] = idx >> 6; bC4[i] = (idx & 63) * 4;
    }

    // stage 0
    {
        float* as = AsBase; float* bs = BsBase;
#pragma unroll
        for (int i = 0; i < 2; i++)
            cpa16(sptr(&as[aRow[i] * BSA + aC4[i]]),
                  &A[(size_t)(rowBase + aRow[i]) * K + aC4[i]]);
#pragma unroll
        for (int i = 0; i < 4; i++)
            cpa16(sptr(&bs[bRow[i] * BSB + bC4[i]]),
                  &B[(size_t)bRow[i] * N + colBase + bC4[i]]);
        CP_COMMIT();
    }

    float acc[4][8][4];
#pragma unroll
    for (int mt = 0; mt < 4; mt++)
#pragma unroll
        for (int nt = 0; nt < 8; nt++)
#pragma unroll
            for (int r = 0; r < 4; r++) acc[mt][nt][r] = 0.f;

    const int KT = K >> 4;
    for (int t = 0; t < KT; t++) {
        const int cur = t & 1;
        if (t + 1 < KT) {
            float* as = AsBase + (cur ^ 1) * 128 * BSA;
            float* bs = BsBase + (cur ^ 1) * 16 * BSB;
            const int k0 = (t + 1) * 16;
#pragma unroll
            for (int i = 0; i < 2; i++)
                cpa16(sptr(&as[aRow[i] * BSA + aC4[i]]),
                      &A[(size_t)(rowBase + aRow[i]) * K + k0 + aC4[i]]);
#pragma unroll
            for (int i = 0; i < 4; i++)
                cpa16(sptr(&bs[bRow[i] * BSB + bC4[i]]),
                      &B[(size_t)(k0 + bRow[i]) * N + colBase + bC4[i]]);
            CP_COMMIT();
            CP_WAIT(1);
        } else {
            CP_WAIT(0);
        }
        __syncthreads();

        const float* as = AsBase + cur * 128 * BSA;
        const float* bs = BsBase + cur * 16 * BSB;
#pragma unroll
        for (int ks = 0; ks < 2; ks++) {
            const int k8 = ks * 8;
            uint32_t a[4][4];
#pragma unroll
            for (int mt = 0; mt < 4; mt++) {
                const int mb = wm + mt * 16;
                a[mt][0] = fb(as[(mb + g) * BSA + k8 + tg]);
                a[mt][1] = fb(as[(mb + g + 8) * BSA + k8 + tg]);
                a[mt][2] = fb(as[(mb + g) * BSA + k8 + tg + 4]);
                a[mt][3] = fb(as[(mb + g + 8) * BSA + k8 + tg + 4]);
            }
#pragma unroll
            for (int nt = 0; nt < 8; nt++) {
                uint32_t b0 = fb(bs[(k8 + tg) * BSB + wn + nt * 8 + g]);
                uint32_t b1 = fb(bs[(k8 + tg + 4) * BSB + wn + nt * 8 + g]);
#pragma unroll
                for (int mt = 0; mt < 4; mt++) mma_tf32(acc[mt][nt], a[mt], b0, b1);
            }
        }
        __syncthreads();
    }

    // epilogue
#pragma unroll
    for (int mt = 0; mt < 4; mt++) {
        const int r0 = rowBase + wm + mt * 16 + g;
#pragma unroll
        for (int nt = 0; nt < 8; nt++) {
            const int col = colBase + wn + nt * 8 + tg * 2;
            const float bx = bias[col], by = bias[col + 1];
            float v00 = acc[mt][nt][0] + bx, v01 = acc[mt][nt][1] + by;
            float v10 = acc[mt][nt][2] + bx, v11 = acc[mt][nt][3] + by;
            if (roundOut) {
                v00 = tf32r(v00); v01 = tf32r(v01);
                v10 = tf32r(v10); v11 = tf32r(v11);
            }
            float2 o0 = {v00, v01}, o1 = {v10, v11};
            *reinterpret_cast<float2*>(&C[(size_t)r0 * N + col]) = o0;
            *reinterpret_cast<float2*>(&C[(size_t)(r0 + 8) * N + col]) = o1;
        }
    }
}

// ---------------------------------------------------------------------------
// TF32 flash attention (causal).  128 threads (4 warps), BQ=128 (32 q rows
// per warp), BKV=64.  qkv is pre-rounded tf32 -> no cvt in loops.
// K/V tiles cp.async double-buffered.  Output rounded to tf32.
// ---------------------------------------------------------------------------
#define QST 68
#define KST 68
#define VST 72
#define ATT_SMEM ((128 * QST + 2 * 64 * KST + 2 * 64 * VST) * 4)

__global__ __launch_bounds__(128)
void attn_tc_kernel(const float* __restrict__ qkv, float* __restrict__ out) {
    extern __shared__ float smem[];
    float* Qs = smem;                            // [128][QST] (reused as Ps)
    float* KsB = smem + 128 * QST;               // [2][64][KST]
    float* VsB = smem + 128 * QST + 2 * 64 * KST;// [2][64][VST]
    float* Ps = Qs;

    const int qb = (gridDim.x - 1) - blockIdx.x;   // heavy blocks first
    const int h = blockIdx.y, b = blockIdx.z;
    const int tid = threadIdx.x;
    const int w = tid >> 5, lane = tid & 31;
    const int g = lane >> 2, tg = lane & 3;

    // K/V cp.async chunk indices (8 chunks each per thread)
    int kvRow[8], kvC4[8];
#pragma unroll
    for (int i = 0; i < 8; i++) {
        int idx = i * 128 + tid;
        kvRow[i] = idx >> 4; kvC4[i] = (idx & 15) * 4;
    }

    // issue K/V tile kt into stage s
    auto issueKV = [&](int s, int kt) {
        float* Ks = KsB + s * 64 * KST;
        float* Vs = VsB + s * 64 * VST;
#pragma unroll
        for (int i = 0; i < 8; i++) {
            const size_t gofs =
                ((size_t)(b * TT + kt * 64 + kvRow[i])) * (3 * CCH) + h * DD + kvC4[i];
            cpa16(sptr(&Ks[kvRow[i] * KST + kvC4[i]]), &qkv[gofs + CCH]);
            cpa16(sptr(&Vs[kvRow[i] * VST + kvC4[i]]), &qkv[gofs + 2 * CCH]);
        }
        CP_COMMIT();
    };

    issueKV(0, 0);

    // Load Q tile 128x64 (already tf32)
#pragma unroll
    for (int i = 0; i < 16; i++) {
        const int idx = i * 128 + tid;
        const int row = idx >> 4, c4 = (idx & 15) * 4;
        const size_t gofs = ((size_t)(b * TT + qb * 128 + row)) * (3 * CCH) + h * DD + c4;
        *reinterpret_cast<float4*>(&Qs[row * QST + c4]) =
            *reinterpret_cast<const float4*>(&qkv[gofs]);
    }
    __syncthreads();

    // Q fragments (0.125 scale is exact in tf32)
    uint32_t qf[2][8][4];
#pragma unroll
    for (int mt = 0; mt < 2; mt++) {
        const int r0 = w * 32 + mt * 16 + g;
#pragma unroll
        for (int ks = 0; ks < 8; ks++) {
            const int d0 = ks * 8;
            qf[mt][ks][0] = fb(0.125f * Qs[r0 * QST + d0 + tg]);
            qf[mt][ks][1] = fb(0.125f * Qs[(r0 + 8) * QST + d0 + tg]);
            qf[mt][ks][2] = fb(0.125f * Qs[r0 * QST + d0 + tg + 4]);
            qf[mt][ks][3] = fb(0.125f * Qs[(r0 + 8) * QST + d0 + tg + 4]);
        }
    }

    float O[2][8][4];
#pragma unroll
    for (int mt = 0; mt < 2; mt++)
#pragma unroll
        for (int nt = 0; nt < 8; nt++)
#pragma unroll
            for (int r = 0; r < 4; r++) O[mt][nt][r] = 0.f;
    float mx[2][2] = {{NEG_BIG, NEG_BIG}, {NEG_BIG, NEG_BIG}};
    float l[2][2] = {{0.f, 0.f}, {0.f, 0.f}};

    const int qmin = qb * 128 + w * 32;
    const int ktmax = 2 * qb + 1;

    for (int kt = 0; kt <= ktmax; kt++) {
        const int cur = kt & 1;
        if (kt < ktmax) { issueKV(cur ^ 1, kt + 1); CP_WAIT(1); }
        else            { CP_WAIT(0); }
        __syncthreads();

        const float* Ks = KsB + cur * 64 * KST;
        const float* Vs = VsB + cur * 64 * VST;

        int rem = ((qmin + 31 - kt * 64) >> 3) + 1;
        const int ntc = rem < 8 ? rem : 8;
        if (ntc > 0) {
            const bool needmask = (kt * 64 + 63 > qmin);

            // S = Q K^T
            float s[2][8][4];
#pragma unroll
            for (int nt = 0; nt < 8; nt++) {
                if (nt < ntc) {
#pragma unroll
                    for (int r = 0; r < 4; r++) { s[0][nt][r] = 0.f; s[1][nt][r] = 0.f; }
#pragma unroll
                    for (int ks = 0; ks < 8; ks++) {
                        uint32_t b0 = fb(Ks[(nt * 8 + g) * KST + ks * 8 + tg]);
                        uint32_t b1 = fb(Ks[(nt * 8 + g) * KST + ks * 8 + tg + 4]);
                        mma_tf32(s[0][nt], qf[0][ks], b0, b1);
                        mma_tf32(s[1][nt], qf[1][ks], b0, b1);
                    }
                }
            }

            if (needmask) {
#pragma unroll
                for (int mt = 0; mt < 2; mt++) {
                    const int r0 = qmin + mt * 16 + g, r1 = r0 + 8;
#pragma unroll
                    for (int nt = 0; nt < 8; nt++) {
                        if (nt < ntc) {
                            const int c0 = kt * 64 + nt * 8 + tg * 2, c1 = c0 + 1;
                            if (c0 > r0) s[mt][nt][0] = NEG_BIG;
                            if (c1 > r0) s[mt][nt][1] = NEG_BIG;
                            if (c0 > r1) s[mt][nt][2] = NEG_BIG;
                            if (c1 > r1) s[mt][nt][3] = NEG_BIG;
                        }
                    }
                }
            }

            // online softmax
#pragma unroll
            for (int mt = 0; mt < 2; mt++) {
                float mt0 = NEG_BIG, mt1 = NEG_BIG;
#pragma unroll
                for (int nt = 0; nt < 8; nt++) {
                    if (nt < ntc) {
                        mt0 = fmaxf(mt0, fmaxf(s[mt][nt][0], s[mt][nt][1]));
                        mt1 = fmaxf(mt1, fmaxf(s[mt][nt][2], s[mt][nt][3]));
                    }
                }
                mt0 = fmaxf(mt0, __shfl_xor_sync(0xffffffffu, mt0, 1));
                mt0 = fmaxf(mt0, __shfl_xor_sync(0xffffffffu, mt0, 2));
                mt1 = fmaxf(mt1, __shfl_xor_sync(0xffffffffu, mt1, 1));
                mt1 = fmaxf(mt1, __shfl_xor_sync(0xffffffffu, mt1, 2));
                const float nm0 = fmaxf(mx[mt][0], mt0), nm1 = fmaxf(mx[mt][1], mt1);
                const float c0 = __expf(mx[mt][0] - nm0), c1 = __expf(mx[mt][1] - nm1);
                float rs0 = 0.f, rs1 = 0.f;
#pragma unroll
                for (int nt = 0; nt < 8; nt++) {
                    if (nt < ntc) {
                        float p0 = __expf(s[mt][nt][0] - nm0);
                        float p1 = __expf(s[mt][nt][1] - nm0);
                        float p2 = __expf(s[mt][nt][2] - nm1);
                        float p3 = __expf(s[mt][nt][3] - nm1);
                        s[mt][nt][0] = p0; s[mt][nt][1] = p1;
                        s[mt][nt][2] = p2; s[mt][nt][3] = p3;
                        rs0 += p0 + p1; rs1 += p2 + p3;
                    }
                }
                rs0 += __shfl_xor_sync(0xffffffffu, rs0, 1);
                rs0 += __shfl_xor_sync(0xffffffffu, rs0, 2);
                rs1 += __shfl_xor_sync(0xffffffffu, rs1, 1);
                rs1 += __shfl_xor_sync(0xffffffffu, rs1, 2);
                l[mt][0] = l[mt][0] * c0 + rs0;
                l[mt][1] = l[mt][1] * c1 + rs1;
                mx[mt][0] = nm0; mx[mt][1] = nm1;
#pragma unroll
                for (int nt = 0; nt < 8; nt++) {
                    O[mt][nt][0] *= c0; O[mt][nt][1] *= c0;
                    O[mt][nt][2] *= c1; O[mt][nt][3] *= c1;
                }
            }

            // stage P (tf32)
#pragma unroll
            for (int mt = 0; mt < 2; mt++) {
                const int r0 = w * 32 + mt * 16 + g;
#pragma unroll
                for (int nt = 0; nt < 8; nt++) {
                    if (nt < ntc) {
                        float2 p0 = {tf32r(s[mt][nt][0]), tf32r(s[mt][nt][1])};
                        float2 p1 = {tf32r(s[mt][nt][2]), tf32r(s[mt][nt][3])};
                        *reinterpret_cast<float2*>(&Ps[r0 * QST + nt * 8 + tg * 2]) = p0;
                        *reinterpret_cast<float2*>(&Ps[(r0 + 8) * QST + nt * 8 + tg * 2]) = p1;
                    }
                }
            }
            __syncwarp();

            // O += P V
#pragma unroll
            for (int ks = 0; ks < 8; ks++) {
                if (ks < ntc) {
                    uint32_t a0[4], a1[4];
                    const int rA = w * 32 + g;
                    a0[0] = fb(Ps[rA * QST + ks * 8 + tg]);
                    a0[1] = fb(Ps[(rA + 8) * QST + ks * 8 + tg]);
                    a0[2] = fb(Ps[rA * QST + ks * 8 + tg + 4]);
                    a0[3] = fb(Ps[(rA + 8) * QST + ks * 8 + tg + 4]);
                    a1[0] = fb(Ps[(rA + 16) * QST + ks * 8 + tg]);
                    a1[1] = fb(Ps[(rA + 24) * QST + ks * 8 + tg]);
                    a1[2] = fb(Ps[(rA + 16) * QST + ks * 8 + tg + 4]);
                    a1[3] = fb(Ps[(rA + 24) * QST + ks * 8 + tg + 4]);
#pragma unroll
                    for (int nt = 0; nt < 8; nt++) {
                        uint32_t b0 = fb(Vs[(ks * 8 + tg) * VST + nt * 8 + g]);
                        uint32_t b1 = fb(Vs[(ks * 8 + tg + 4) * VST + nt * 8 + g]);
                        mma_tf32(O[0][nt], a0, b0, b1);
                        mma_tf32(O[1][nt], a1, b0, b1);
                    }
                }
            }
        }
        __syncthreads();
    }

    // epilogue (round to tf32: feeds proj GEMM)
#pragma unroll
    for (int mt = 0; mt < 2; mt++) {
        const float inv0 = 1.f / l[mt][0], inv1 = 1.f / l[mt][1];
        const int row0 = qb * 128 + w * 32 + mt * 16 + g;
#pragma unroll
        for (int nt = 0; nt < 8; nt++) {
            const int col = h * DD + nt * 8 + tg * 2;
            float2 o0 = {tf32r(O[mt][nt][0] * inv0), tf32r(O[mt][nt][1] * inv0)};
            float2 o1 = {tf32r(O[mt][nt][2] * inv1), tf32r(O[mt][nt][3] * inv1)};
            *reinterpret_cast<float2*>(&out[(size_t)(b * TT + row0) * CCH + col]) = o0;
            *reinterpret_cast<float2*>(&out[(size_t)(b * TT + row0 + 8) * CCH + col]) = o1;
        }
    }
}

// ---------------------------------------------------------------------------
extern "C" void kernel_launch(void* const* d_in, const int* in_sizes, int n_in,
                              void* d_out, int out_size) {
    const float* x     = (const float*)d_in[0];
    const float* Wqkv  = (const float*)d_in[1];
    const float* bqkv  = (const float*)d_in[2];
    const float* Wproj = (const float*)d_in[3];
    const float* bproj = (const float*)d_in[4];
    float* out = (float*)d_out;

    float *qkv, *att, *x32, *wqkv, *wproj;
    cudaGetSymbolAddress((void**)&qkv, g_qkv);
    cudaGetSymbolAddress((void**)&att, g_att);
    cudaGetSymbolAddress((void**)&x32, g_x32);
    cudaGetSymbolAddress((void**)&wqkv, g_wqkv);
    cudaGetSymbolAddress((void**)&wproj, g_wproj);

    // 0) pre-round inputs to tf32
    {
        int n4x = MROWS * CCH / 4;
        int n4q = CCH * 3 * CCH / 4;
        int n4p = CCH * CCH / 4;
        cvt_tf32_kernel<<<(n4x + 255) / 256, 256>>>(x, x32, n4x);
        cvt_tf32_kernel<<<(n4q + 255) / 256, 256>>>(Wqkv, wqkv, n4q);
        cvt_tf32_kernel<<<(n4p + 255) / 256, 256>>>(Wproj, wproj, n4p);
    }
    // 1) QKV projection (output rounded to tf32)
    {
        cudaFuncSetAttribute(gemm_tf32_cp, cudaFuncAttributeMaxDynamicSharedMemorySize,
                             GEMM_SMEM);
        dim3 grid(3 * CCH / 256, MROWS / 128);
        gemm_tf32_cp<<<grid, 256, GEMM_SMEM>>>(x32, wqkv, bqkv, qkv,
                                               MROWS, 3 * CCH, CCH, 1);
    }
    // 2) Flash attention
    {
        cudaFuncSetAttribute(attn_tc_kernel, cudaFuncAttributeMaxDynamicSharedMemorySize,
                             ATT_SMEM);
        dim3 grid(TT / 128, HH, BB);
        attn_tc_kernel<<<grid, 128, ATT_SMEM>>>(qkv, att);
    }
    // 3) Output projection (full fp32 out)
    {
        dim3 grid(CCH / 256, MROWS / 128);
        gemm_tf32_cp<<<grid, 256, GEMM_SMEM>>>(att, wproj, bproj, out,
                                               MROWS, CCH, CCH, 0);
    }
}

// round 8
// speedup vs baseline: 1.9360x; 1.9360x over previous
#include <cuda_runtime.h>
#include <cuda_fp16.h>
#include <cstdint>

#define BB 2
#define TT 2048
#define CCH 1024
#define HH 16
#define DD 64
#define MROWS (BB * TT)       // 4096
#define NEG_BIG (-1e30f)

// Scratch (half-precision working set)
__device__ __half g_qkv[(size_t)MROWS * 3 * CCH];
__device__ __half g_att[(size_t)MROWS * CCH];
__device__ __half g_xh[(size_t)MROWS * CCH];
__device__ __half g_wqkv[(size_t)CCH * 3 * CCH];
__device__ __half g_wproj[(size_t)CCH * CCH];

// ---------------------------------------------------------------------------
// Helpers
// ---------------------------------------------------------------------------
__device__ __forceinline__ uint32_t sptr(const void* p) {
    return (uint32_t)__cvta_generic_to_shared(p);
}
__device__ __forceinline__ void cpa16(uint32_t d, const void* s) {
    asm volatile("cp.async.ca.shared.global [%0], [%1], 16;" :: "r"(d), "l"(s));
}
#define CP_COMMIT() asm volatile("cp.async.commit_group;" ::)
#define CP_WAIT(N)  asm volatile("cp.async.wait_group %0;" :: "n"(N))

__device__ __forceinline__ void ldsm4(uint32_t& r0, uint32_t& r1, uint32_t& r2,
                                      uint32_t& r3, uint32_t addr) {
    asm volatile("ldmatrix.sync.aligned.m8n8.x4.shared.b16 {%0,%1,%2,%3}, [%4];"
                 : "=r"(r0), "=r"(r1), "=r"(r2), "=r"(r3) : "r"(addr));
}
__device__ __forceinline__ void ldsm4t(uint32_t& r0, uint32_t& r1, uint32_t& r2,
                                       uint32_t& r3, uint32_t addr) {
    asm volatile("ldmatrix.sync.aligned.m8n8.x4.trans.shared.b16 {%0,%1,%2,%3}, [%4];"
                 : "=r"(r0), "=r"(r1), "=r"(r2), "=r"(r3) : "r"(addr));
}
__device__ __forceinline__ void mma16816(float c[4], const uint32_t a[4],
                                         uint32_t b0, uint32_t b1) {
    asm volatile(
        "mma.sync.aligned.m16n8k16.row.col.f32.f16.f16.f32 "
        "{%0,%1,%2,%3}, {%4,%5,%6,%7}, {%8,%9}, {%0,%1,%2,%3};\n"
        : "+f"(c[0]), "+f"(c[1]), "+f"(c[2]), "+f"(c[3])
        : "r"(a[0]), "r"(a[1]), "r"(a[2]), "r"(a[3]), "r"(b0), "r"(b1));
}
__device__ __forceinline__ uint32_t h2u(__half2 h) { return *reinterpret_cast<uint32_t*>(&h); }

// ---------------------------------------------------------------------------
// fp32 -> fp16 conversion pre-pass
// ---------------------------------------------------------------------------
__global__ void cvt_f2h(const float* __restrict__ src, __half* __restrict__ dst, int n4) {
    int i = blockIdx.x * blockDim.x + threadIdx.x;
    if (i < n4) {
        float4 v = reinterpret_cast<const float4*>(src)[i];
        __half2* d = reinterpret_cast<__half2*>(dst) + 2 * i;
        d[0] = __floats2half2_rn(v.x, v.y);
        d[1] = __floats2half2_rn(v.z, v.w);
    }
}

// ---------------------------------------------------------------------------
// FP16 GEMM + fp32 bias.  Block 128(M) x 256(N), 256 thr (8 warps, 64x64 warp
// tiles), BK=32, 2-stage cp.async.  A smem [m][k] stride 40h (80B); B smem
// [k][n] stride 264h (528B) + ldmatrix.trans.  Output: half (Ch) or float (Cf).
// ---------------------------------------------------------------------------
#define GAS 40
#define GBS 264
#define GEMM_SMEM ((2 * 128 * GAS + 2 * 32 * GBS) * 2)

__global__ __launch_bounds__(256)
void gemm_f16(const __half* __restrict__ A, const __half* __restrict__ B,
              const float* __restrict__ bias, __half* __restrict__ Ch,
              float* __restrict__ Cf, int M, int N, int K) {
    extern __shared__ __half sm[];
    __half* AsB = sm;                    // [2][128][GAS]
    __half* BsB = sm + 2 * 128 * GAS;    // [2][32][GBS]

    const int tid = threadIdx.x;
    const int w = tid >> 5, lane = tid & 31;
    const int g = lane >> 2, tg = lane & 3;
    const int wm = (w & 1) * 64, wn = (w >> 1) * 64;
    const int rowBase = blockIdx.y * 128;
    const int colBase = blockIdx.x * 256;

    // cp.async indices
    int aRow[2], aC8[2], bRow[4], bC8[4];
#pragma unroll
    for (int i = 0; i < 2; i++) {
        int idx = i * 256 + tid;
        aRow[i] = idx >> 2; aC8[i] = (idx & 3) * 8;
    }
#pragma unroll
    for (int i = 0; i < 4; i++) {
        int idx = i * 256 + tid;
        bRow[i] = idx >> 5; bC8[i] = (idx & 31) * 8;
    }

    // ldmatrix lane address components
    const int aLrow = lane & 15, aLk = (lane >> 4) * 8;                 // A frags
    const int bLk = ((lane >> 3) & 1) * 8 + (lane & 7), bLn = (lane >> 4) * 8;  // B frags

    auto issue = [&](int stage, int k0) {
        __half* as = AsB + stage * 128 * GAS;
        __half* bs = BsB + stage * 32 * GBS;
#pragma unroll
        for (int i = 0; i < 2; i++)
            cpa16(sptr(&as[aRow[i] * GAS + aC8[i]]),
                  &A[(size_t)(rowBase + aRow[i]) * K + k0 + aC8[i]]);
#pragma unroll
        for (int i = 0; i < 4; i++)
            cpa16(sptr(&bs[bRow[i] * GBS + bC8[i]]),
                  &B[(size_t)(k0 + bRow[i]) * N + colBase + bC8[i]]);
        CP_COMMIT();
    };

    issue(0, 0);

    float acc[4][8][4];
#pragma unroll
    for (int mt = 0; mt < 4; mt++)
#pragma unroll
        for (int nt = 0; nt < 8; nt++)
#pragma unroll
            for (int r = 0; r < 4; r++) acc[mt][nt][r] = 0.f;

    const int KT = K >> 5;
    for (int t = 0; t < KT; t++) {
        const int cur = t & 1;
        if (t + 1 < KT) { issue(cur ^ 1, (t + 1) * 32); CP_WAIT(1); }
        else            { CP_WAIT(0); }
        __syncthreads();

        const __half* as = AsB + cur * 128 * GAS;
        const __half* bs = BsB + cur * 32 * GBS;
#pragma unroll
        for (int s = 0; s < 2; s++) {   // two k16 steps per BK=32
            const int k16 = s * 16;
            uint32_t a[4][4];
#pragma unroll
            for (int mt = 0; mt < 4; mt++)
                ldsm4(a[mt][0], a[mt][1], a[mt][2], a[mt][3],
                      sptr(&as[(wm + mt * 16 + aLrow) * GAS + k16 + aLk]));
#pragma unroll
            for (int ntp = 0; ntp < 4; ntp++) {
                uint32_t b0e, b1e, b0o, b1o;
                ldsm4t(b0e, b1e, b0o, b1o,
                       sptr(&bs[(k16 + bLk) * GBS + wn + ntp * 16 + bLn]));
#pragma unroll
                for (int mt = 0; mt < 4; mt++) {
                    mma16816(acc[mt][2 * ntp], a[mt], b0e, b1e);
                    mma16816(acc[mt][2 * ntp + 1], a[mt], b0o, b1o);
                }
            }
        }
        __syncthreads();
    }

    // epilogue
#pragma unroll
    for (int mt = 0; mt < 4; mt++) {
        const int r0 = rowBase + wm + mt * 16 + g;
#pragma unroll
        for (int nt = 0; nt < 8; nt++) {
            const int col = colBase + wn + nt * 8 + tg * 2;
            const float bx = bias[col], by = bias[col + 1];
            float v00 = acc[mt][nt][0] + bx, v01 = acc[mt][nt][1] + by;
            float v10 = acc[mt][nt][2] + bx, v11 = acc[mt][nt][3] + by;
            if (Cf) {
                float2 o0 = {v00, v01}, o1 = {v10, v11};
                *reinterpret_cast<float2*>(&Cf[(size_t)r0 * N + col]) = o0;
                *reinterpret_cast<float2*>(&Cf[(size_t)(r0 + 8) * N + col]) = o1;
            } else {
                *reinterpret_cast<__half2*>(&Ch[(size_t)r0 * N + col]) =
                    __floats2half2_rn(v00, v01);
                *reinterpret_cast<__half2*>(&Ch[(size_t)(r0 + 8) * N + col]) =
                    __floats2half2_rn(v10, v11);
            }
        }
    }
}

// ---------------------------------------------------------------------------
// FP16 flash attention (causal).  128 thr (4 warps), BQ=128 (32 rows/warp),
// BKV=64, cp.async double-buffered K/V.  P stays in registers (accumulator
// layout == A-fragment layout).  Output half.
// ---------------------------------------------------------------------------
#define AS 72   // smem row stride in halves (144B)
#define ATT_SMEM ((128 * AS + 2 * 64 * AS + 2 * 64 * AS) * 2)

__global__ __launch_bounds__(128)
void attn_f16(const __half* __restrict__ qkv, __half* __restrict__ out) {
    extern __shared__ __half smh[];
    __half* Qs = smh;                         // [128][AS]
    __half* KsB = smh + 128 * AS;             // [2][64][AS]
    __half* VsB = smh + 128 * AS + 2 * 64 * AS;

    const int qb = (gridDim.x - 1) - blockIdx.x;
    const int h = blockIdx.y, b = blockIdx.z;
    const int tid = threadIdx.x;
    const int w = tid >> 5, lane = tid & 31;
    const int g = lane >> 2, tg = lane & 3;

    // ldmatrix lane address components
    const int aLrow = lane & 15, aLk = (lane >> 4) * 8;                       // Q (A frag)
    const int kLn = ((lane >> 4) << 3) + (lane & 7), kLk = ((lane >> 3) & 1) * 8;  // K (plain)
    const int vLk = ((lane >> 3) & 1) * 8 + (lane & 7), vLn = (lane >> 4) * 8;     // V (trans)

    // K/V cp.async indices: 4 chunks each
    int kvRow[4], kvC8[4];
#pragma unroll
    for (int i = 0; i < 4; i++) {
        int idx = i * 128 + tid;
        kvRow[i] = idx >> 3; kvC8[i] = (idx & 7) * 8;
    }

    auto issueKV = [&](int stage, int kt) {
        __half* Ks = KsB + stage * 64 * AS;
        __half* Vs = VsB + stage * 64 * AS;
#pragma unroll
        for (int i = 0; i < 4; i++) {
            const size_t gofs =
                ((size_t)(b * TT + kt * 64 + kvRow[i])) * (3 * CCH) + h * DD + kvC8[i];
            cpa16(sptr(&Ks[kvRow[i] * AS + kvC8[i]]), &qkv[gofs + CCH]);
            cpa16(sptr(&Vs[kvRow[i] * AS + kvC8[i]]), &qkv[gofs + 2 * CCH]);
        }
        CP_COMMIT();
    };

    issueKV(0, 0);

    // Q tile 128x64 (plain ld/st)
#pragma unroll
    for (int i = 0; i < 8; i++) {
        const int idx = i * 128 + tid;
        const int row = idx >> 3, c8 = (idx & 7) * 8;
        const size_t gofs = ((size_t)(b * TT + qb * 128 + row)) * (3 * CCH) + h * DD + c8;
        *reinterpret_cast<uint4*>(&Qs[row * AS + c8]) =
            *reinterpret_cast<const uint4*>(&qkv[gofs]);
    }
    __syncthreads();

    // Q fragments, scale 0.125 folded (exact in fp16)
    uint32_t qf[2][4][4];
    {
        const __half2 sc = __float2half2_rn(0.125f);
#pragma unroll
        for (int mt = 0; mt < 2; mt++)
#pragma unroll
            for (int s = 0; s < 4; s++) {
                uint32_t r0, r1, r2, r3;
                ldsm4(r0, r1, r2, r3,
                      sptr(&Qs[(w * 32 + mt * 16 + aLrow) * AS + s * 16 + aLk]));
                qf[mt][s][0] = h2u(__hmul2(*reinterpret_cast<__half2*>(&r0), sc));
                qf[mt][s][1] = h2u(__hmul2(*reinterpret_cast<__half2*>(&r1), sc));
                qf[mt][s][2] = h2u(__hmul2(*reinterpret_cast<__half2*>(&r2), sc));
                qf[mt][s][3] = h2u(__hmul2(*reinterpret_cast<__half2*>(&r3), sc));
            }
    }

    float O[2][8][4];
#pragma unroll
    for (int mt = 0; mt < 2; mt++)
#pragma unroll
        for (int nt = 0; nt < 8; nt++)
#pragma unroll
            for (int r = 0; r < 4; r++) O[mt][nt][r] = 0.f;
    float mx[2][2] = {{NEG_BIG, NEG_BIG}, {NEG_BIG, NEG_BIG}};
    float l[2][2] = {{0.f, 0.f}, {0.f, 0.f}};

    const int qmin = qb * 128 + w * 32;
    const int ktmax = 2 * qb + 1;

    for (int kt = 0; kt <= ktmax; kt++) {
        const int cur = kt & 1;
        if (kt < ktmax) { issueKV(cur ^ 1, kt + 1); CP_WAIT(1); }
        else            { CP_WAIT(0); }
        __syncthreads();

        const __half* Ks = KsB + cur * 64 * AS;
        const __half* Vs = VsB + cur * 64 * AS;

        int rem = ((qmin + 31 - kt * 64) >> 3) + 1;
        const int ntc = rem < 8 ? rem : 8;
        if (ntc > 0) {
            const bool needmask = (kt * 64 + 63 > qmin);

            float s[2][8][4];
#pragma unroll
            for (int nt = 0; nt < 8; nt++)
#pragma unroll
                for (int r = 0; r < 4; r++) { s[0][nt][r] = 0.f; s[1][nt][r] = 0.f; }

            // S = (Q/8) K^T
#pragma unroll
            for (int ks = 0; ks < 4; ks++) {
#pragma unroll
                for (int ntp = 0; ntp < 4; ntp++) {
                    if (2 * ntp < ntc) {
                        uint32_t b0e, b1e, b0o, b1o;
                        ldsm4(b0e, b1e, b0o, b1o,
                              sptr(&Ks[(ntp * 16 + kLn) * AS + ks * 16 + kLk]));
                        mma16816(s[0][2 * ntp], qf[0][ks], b0e, b1e);
                        mma16816(s[1][2 * ntp], qf[1][ks], b0e, b1e);
                        mma16816(s[0][2 * ntp + 1], qf[0][ks], b0o, b1o);
                        mma16816(s[1][2 * ntp + 1], qf[1][ks], b0o, b1o);
                    }
                }
            }

            if (needmask) {
#pragma unroll
                for (int mt = 0; mt < 2; mt++) {
                    const int r0 = qmin + mt * 16 + g, r1 = r0 + 8;
#pragma unroll
                    for (int nt = 0; nt < 8; nt++) {
                        if (nt < ntc) {
                            const int c0 = kt * 64 + nt * 8 + tg * 2, c1 = c0 + 1;
                            if (c0 > r0) s[mt][nt][0] = NEG_BIG;
                            if (c1 > r0) s[mt][nt][1] = NEG_BIG;
                            if (c0 > r1) s[mt][nt][2] = NEG_BIG;
                            if (c1 > r1) s[mt][nt][3] = NEG_BIG;
                        } else {
                            s[mt][nt][0] = NEG_BIG; s[mt][nt][1] = NEG_BIG;
                            s[mt][nt][2] = NEG_BIG; s[mt][nt][3] = NEG_BIG;
                        }
                    }
                }
            }

            // online softmax
#pragma unroll
            for (int mt = 0; mt < 2; mt++) {
                float mt0 = NEG_BIG, mt1 = NEG_BIG;
#pragma unroll
                for (int nt = 0; nt < 8; nt++) {
                    if (nt < ntc) {
                        mt0 = fmaxf(mt0, fmaxf(s[mt][nt][0], s[mt][nt][1]));
                        mt1 = fmaxf(mt1, fmaxf(s[mt][nt][2], s[mt][nt][3]));
                    }
                }
                mt0 = fmaxf(mt0, __shfl_xor_sync(0xffffffffu, mt0, 1));
                mt0 = fmaxf(mt0, __shfl_xor_sync(0xffffffffu, mt0, 2));
                mt1 = fmaxf(mt1, __shfl_xor_sync(0xffffffffu, mt1, 1));
                mt1 = fmaxf(mt1, __shfl_xor_sync(0xffffffffu, mt1, 2));
                const float nm0 = fmaxf(mx[mt][0], mt0), nm1 = fmaxf(mx[mt][1], mt1);
                const float c0 = __expf(mx[mt][0] - nm0), c1 = __expf(mx[mt][1] - nm1);
                float rs0 = 0.f, rs1 = 0.f;
#pragma unroll
                for (int nt = 0; nt < 8; nt++) {
                    if (nt < ntc) {
                        float p0 = __expf(s[mt][nt][0] - nm0);
                        float p1 = __expf(s[mt][nt][1] - nm0);
                        float p2 = __expf(s[mt][nt][2] - nm1);
                        float p3 = __expf(s[mt][nt][3] - nm1);
                        s[mt][nt][0] = p0; s[mt][nt][1] = p1;
                        s[mt][nt][2] = p2; s[mt][nt][3] = p3;
                        rs0 += p0 + p1; rs1 += p2 + p3;
                    } else {
                        s[mt][nt][0] = 0.f; s[mt][nt][1] = 0.f;
                        s[mt][nt][2] = 0.f; s[mt][nt][3] = 0.f;
                    }
                }
                rs0 += __shfl_xor_sync(0xffffffffu, rs0, 1);
                rs0 += __shfl_xor_sync(0xffffffffu, rs0, 2);
                rs1 += __shfl_xor_sync(0xffffffffu, rs1, 1);
                rs1 += __shfl_xor_sync(0xffffffffu, rs1, 2);
                l[mt][0] = l[mt][0] * c0 + rs0;
                l[mt][1] = l[mt][1] * c1 + rs1;
                mx[mt][0] = nm0; mx[mt][1] = nm1;
#pragma unroll
                for (int nt = 0; nt < 8; nt++) {
                    O[mt][nt][0] *= c0; O[mt][nt][1] *= c0;
                    O[mt][nt][2] *= c1; O[mt][nt][3] *= c1;
                }
            }

            // O += P V  (P direct from S accumulators — no smem)
            const int spc = (ntc + 1) >> 1;
#pragma unroll
            for (int sp = 0; sp < 4; sp++) {
                if (sp < spc) {
                    uint32_t pa[2][4];
#pragma unroll
                    for (int mt = 0; mt < 2; mt++) {
                        pa[mt][0] = h2u(__floats2half2_rn(s[mt][2 * sp][0], s[mt][2 * sp][1]));
                        pa[mt][1] = h2u(__floats2half2_rn(s[mt][2 * sp][2], s[mt][2 * sp][3]));
                        pa[mt][2] = h2u(__floats2half2_rn(s[mt][2 * sp + 1][0], s[mt][2 * sp + 1][1]));
                        pa[mt][3] = h2u(__floats2half2_rn(s[mt][2 * sp + 1][2], s[mt][2 * sp + 1][3]));
                    }
#pragma unroll
                    for (int ntp = 0; ntp < 4; ntp++) {
                        uint32_t b0e, b1e, b0o, b1o;
                        ldsm4t(b0e, b1e, b0o, b1o,
                               sptr(&Vs[(sp * 16 + vLk) * AS + ntp * 16 + vLn]));
                        mma16816(O[0][2 * ntp], pa[0], b0e, b1e);
                        mma16816(O[1][2 * ntp], pa[1], b0e, b1e);
                        mma16816(O[0][2 * ntp + 1], pa[0], b0o, b1o);
                        mma16816(O[1][2 * ntp + 1], pa[1], b0o, b1o);
                    }
                }
            }
        }
        __syncthreads();
    }

    // epilogue (half, feeds proj GEMM)
#pragma unroll
    for (int mt = 0; mt < 2; mt++) {
        const float inv0 = 1.f / l[mt][0], inv1 = 1.f / l[mt][1];
        const int row0 = qb * 128 + w * 32 + mt * 16 + g;
#pragma unroll
        for (int nt = 0; nt < 8; nt++) {
            const int col = h * DD + nt * 8 + tg * 2;
            *reinterpret_cast<__half2*>(&out[(size_t)(b * TT + row0) * CCH + col]) =
                __floats2half2_rn(O[mt][nt][0] * inv0, O[mt][nt][1] * inv0);
            *reinterpret_cast<__half2*>(&out[(size_t)(b * TT + row0 + 8) * CCH + col]) =
                __floats2half2_rn(O[mt][nt][2] * inv1, O[mt][nt][3] * inv1);
        }
    }
}

// ---------------------------------------------------------------------------
extern "C" void kernel_launch(void* const* d_in, const int* in_sizes, int n_in,
                              void* d_out, int out_size) {
    const float* x     = (const float*)d_in[0];
    const float* Wqkv  = (const float*)d_in[1];
    const float* bqkv  = (const float*)d_in[2];
    const float* Wproj = (const float*)d_in[3];
    const float* bproj = (const float*)d_in[4];
    float* out = (float*)d_out;

    __half *qkv, *att, *xh, *wqkv, *wproj;
    cudaGetSymbolAddress((void**)&qkv, g_qkv);
    cudaGetSymbolAddress((void**)&att, g_att);
    cudaGetSymbolAddress((void**)&xh, g_xh);
    cudaGetSymbolAddress((void**)&wqkv, g_wqkv);
    cudaGetSymbolAddress((void**)&wproj, g_wproj);

    // 0) fp32 -> fp16 pre-pass
    {
        int n4x = MROWS * CCH / 4;
        int n4q = CCH * 3 * CCH / 4;
        int n4p = CCH * CCH / 4;
        cvt_f2h<<<(n4x + 255) / 256, 256>>>(x, xh, n4x);
        cvt_f2h<<<(n4q + 255) / 256, 256>>>(Wqkv, wqkv, n4q);
        cvt_f2h<<<(n4p + 255) / 256, 256>>>(Wproj, wproj, n4p);
    }
    // 1) QKV projection -> half
    {
        cudaFuncSetAttribute(gemm_f16, cudaFuncAttributeMaxDynamicSharedMemorySize,
                             GEMM_SMEM);
        dim3 grid(3 * CCH / 256, MROWS / 128);
        gemm_f16<<<grid, 256, GEMM_SMEM>>>(xh, wqkv, bqkv, qkv, nullptr,
                                           MROWS, 3 * CCH, CCH);
    }
    // 2) Flash attention -> half
    {
        cudaFuncSetAttribute(attn_f16, cudaFuncAttributeMaxDynamicSharedMemorySize,
                             ATT_SMEM);
        dim3 grid(TT / 128, HH, BB);
        attn_f16<<<grid, 128, ATT_SMEM>>>(qkv, att);
    }
    // 3) Output projection -> fp32
    {
        dim3 grid(CCH / 256, MROWS / 128);
        gemm_f16<<<grid, 256, GEMM_SMEM>>>(att, wproj, bproj, nullptr, out,
                                           MROWS, CCH, CCH);
    }
}